// round 6
// baseline (speedup 1.0000x reference)
#include <cuda_runtime.h>
#include <math.h>
#include <stdint.h>

#define N_NODES 100000
#define N_EDGES 1600000
#define EF 16
#define EH 32
#define NF 128
#define K1 160             // EH + NF
#define TM 64              // nodes per tile
#define NT_TILES ((N_NODES + TM - 1) / TM)   // 1563
#define SW1 161            // fp32 stride of A / W1t rows (odd -> spread banks)
#define SW2 130            // fp32 stride of H / W2t rows (even -> float2 stores)

// ---------------- device scratch (allocation-free) ----------------
__device__ __align__(16) float g_denom[N_NODES];
__device__ __align__(16) float g_s[(size_t)N_NODES * EF];   // sum of ex * edge_feats
__device__ unsigned int g_ctr;

// ---------------------------------------------------------------------------
// init
// ---------------------------------------------------------------------------
#define NS4 (N_NODES * EF / 4)
#define ND4 (N_NODES / 4)
#define NINIT (NS4 + ND4)
__global__ void init_kernel() {
    int i = blockIdx.x * blockDim.x + threadIdx.x;
    if (i == 0) g_ctr = 0u;
    float4 z = make_float4(0.f, 0.f, 0.f, 0.f);
    if (i < NS4) {
        reinterpret_cast<float4*>(g_s)[i] = z;
    } else if (i < NINIT) {
        reinterpret_cast<float4*>(g_denom)[i - NS4] = z;
    }
}

// ---------------------------------------------------------------------------
// edge kernel: ex = exp(logit); denom[d] += ex; s[d] += ex * feats[e]
// (identical to R5 so the node-kernel delta is attributable)
// ---------------------------------------------------------------------------
__global__ __launch_bounds__(256) void edge_kernel(
    const float* __restrict__ logits,
    const float* __restrict__ feats,
    const int*   __restrict__ dst)
{
    int e = blockIdx.x * blockDim.x + threadIdx.x;

    float ex = __expf(logits[e]);
    int d = dst[e];

    const float4* f4 = reinterpret_cast<const float4*>(feats + (size_t)e * EF);
    float4 q0 = f4[0], q1 = f4[1], q2 = f4[2], q3 = f4[3];

    atomicAdd(&g_denom[d], ex);

    float* sp = &g_s[(size_t)d * EF];
    asm volatile("red.global.add.v4.f32 [%0], {%1, %2, %3, %4};"
                 :: "l"(sp + 0), "f"(ex * q0.x), "f"(ex * q0.y),
                    "f"(ex * q0.z), "f"(ex * q0.w) : "memory");
    asm volatile("red.global.add.v4.f32 [%0], {%1, %2, %3, %4};"
                 :: "l"(sp + 4), "f"(ex * q1.x), "f"(ex * q1.y),
                    "f"(ex * q1.z), "f"(ex * q1.w) : "memory");
    asm volatile("red.global.add.v4.f32 [%0], {%1, %2, %3, %4};"
                 :: "l"(sp + 8), "f"(ex * q2.x), "f"(ex * q2.y),
                    "f"(ex * q2.z), "f"(ex * q2.w) : "memory");
    asm volatile("red.global.add.v4.f32 [%0], {%1, %2, %3, %4};"
                 :: "l"(sp + 12), "f"(ex * q3.x), "f"(ex * q3.y),
                    "f"(ex * q3.z), "f"(ex * q3.w) : "memory");
}

// ---------------------------------------------------------------------------
// node kernel: single-pass TF32 tensor-core MLP (mma.sync m16n8k8)
// ---------------------------------------------------------------------------
// smem layout, float-element offsets
#define O_W1 0
#define O_W2 (O_W1 + NF * SW1)            // 20608
#define O_A  (O_W2 + NF * SW2)            // 37248
#define O_H  (O_A + TM * SW1)             // 47552
#define O_B1 (O_H + TM * SW2)             // 55872
#define O_B2 (O_B1 + NF)                  // 56000
#define O_WET (O_B2 + NF)                 // 56128
#define O_BET (O_WET + EF * EH)           // 56640
#define SMEM_FLOATS (O_BET + EH)          // 56672
#define SMEM_BYTES (SMEM_FLOATS * 4)      // 226,688 B

#define MMA_TF32(c, a0, a1, a2, a3, b0, b1)                                   \
    asm volatile("mma.sync.aligned.m16n8k8.row.col.f32.tf32.tf32.f32 "        \
                 "{%0,%1,%2,%3}, {%4,%5,%6,%7}, {%8,%9}, {%0,%1,%2,%3};"      \
                 : "+f"((c)[0]), "+f"((c)[1]), "+f"((c)[2]), "+f"((c)[3])     \
                 : "r"(a0), "r"(a1), "r"(a2), "r"(a3), "r"(b0), "r"(b1))

__device__ __forceinline__ float tf32r(float x) {
    uint32_t r;
    asm("cvt.rna.tf32.f32 %0, %1;" : "=r"(r) : "f"(x));
    return __uint_as_float(r);
}
__device__ __forceinline__ uint32_t fbits(float x) { return __float_as_uint(x); }

__global__ __launch_bounds__(512, 1) void node_kernel(
    const float* __restrict__ node_feats,
    const float* __restrict__ W_et,
    const float* __restrict__ b_et,
    const float* __restrict__ W1,
    const float* __restrict__ b1,
    const float* __restrict__ W2,
    const float* __restrict__ b2,
    float* __restrict__ out)
{
    __shared__ unsigned s_tile;
    extern __shared__ __align__(16) float smem[];
    float* sW1  = smem + O_W1;   // [NF][SW1]  W1 transposed, tf32-rounded
    float* sW2  = smem + O_W2;   // [NF][SW2]  W2 transposed, tf32-rounded
    float* sA   = smem + O_A;    // [TM][SW1]  input tile, tf32-rounded
    float* sH   = smem + O_H;    // [TM][SW2]  hidden tile, tf32-rounded
    float* sb1  = smem + O_B1;
    float* sb2  = smem + O_B2;
    float* sWet = smem + O_WET;
    float* sbet = smem + O_BET;

    const int tid  = threadIdx.x;
    const int wid  = tid >> 5;
    const int lane = tid & 31;
    const int gq   = lane >> 2;     // fragment row group 0..7
    const int tig  = lane & 3;      // thread-in-group
    const int mi   = wid >> 2;      // m-tile 0..3 (16 nodes each)
    const int ni   = wid & 3;       // n-tile 0..3 (32 cols each)

    if (tid == 0) s_tile = atomicAdd(&g_ctr, 1u);
    __syncthreads();
    unsigned tile = s_tile;
    if (tile >= NT_TILES) return;

    // ---- stage weights (transposed + tf32-rounded) ----
    for (int i = tid; i < K1 * NF; i += 512) {
        int k = i >> 7, n = i & 127;
        sW1[n * SW1 + k] = tf32r(W1[i]);
    }
    for (int i = tid; i < NF * NF; i += 512) {
        int k = i >> 7, n = i & 127;
        sW2[n * SW2 + k] = tf32r(W2[i]);
    }
    if (tid < EF * EH) sWet[tid] = W_et[tid];
    if (tid < EH) sbet[tid] = b_et[tid];
    if (tid < NF) { sb1[tid] = b1[tid]; sb2[tid] = b2[tid]; }
    __syncthreads();

    while (tile < NT_TILES) {
        int base = (int)tile * TM;

        // ---- stage ctx: t = s/denom; et = t @ W_et + b_et; elu ----
        {
            int n = tid >> 3;            // node within tile 0..63
            int p = tid & 7;             // column subgroup
            int node = base + n;
            float t[EF];
            if (node < N_NODES) {
                float den = g_denom[node];
                if (den == 0.0f) den = 1.0f;
                float inv = 1.0f / den;
                const float4* sp = reinterpret_cast<const float4*>(g_s + (size_t)node * EF);
                float4 a = sp[0], b = sp[1], c = sp[2], d = sp[3];
                t[0] = a.x * inv;  t[1] = a.y * inv;  t[2] = a.z * inv;  t[3] = a.w * inv;
                t[4] = b.x * inv;  t[5] = b.y * inv;  t[6] = b.z * inv;  t[7] = b.w * inv;
                t[8] = c.x * inv;  t[9] = c.y * inv;  t[10] = c.z * inv; t[11] = c.w * inv;
                t[12] = d.x * inv; t[13] = d.y * inv; t[14] = d.z * inv; t[15] = d.w * inv;
            } else {
#pragma unroll
                for (int k = 0; k < EF; k++) t[k] = 0.0f;
            }
#pragma unroll
            for (int jj = 0; jj < 4; jj++) {
                int jc = p * 4 + jj;
                float acc = sbet[jc];
#pragma unroll
                for (int k = 0; k < EF; k++)
                    acc = fmaf(t[k], sWet[k * EH + jc], acc);
                float v = (acc > 0.0f) ? acc : expm1f(acc);
                if (node >= N_NODES) v = 0.0f;
                sA[n * SW1 + jc] = tf32r(v);
            }
        }
        // ---- stage node feats (tf32-rounded) ----
        for (int i = tid; i < TM * NF; i += 512) {
            int n = i >> 7, f = i & 127;
            int node = base + n;
            float v = (node < N_NODES) ? node_feats[(size_t)node * NF + f] : 0.0f;
            sA[n * SW1 + EH + f] = tf32r(v);
        }
        __syncthreads();

        // ================= GEMM1: [64 x 160] @ [160 x 128] =================
        float acc[4][4];
#pragma unroll
        for (int s = 0; s < 4; s++) {
            int col0 = ni * 32 + s * 8 + tig * 2;
            acc[s][0] = sb1[col0];
            acc[s][1] = sb1[col0 + 1];
            acc[s][2] = acc[s][0];
            acc[s][3] = acc[s][1];
        }
        {
            const float* aB = sA + (mi * 16 + gq) * SW1 + tig;
            const float* bB = sW1 + (ni * 32 + gq) * SW1 + tig;
#pragma unroll 4
            for (int kc = 0; kc < K1 / 8; kc++) {
                int ko = kc * 8;
                uint32_t a0 = fbits(aB[ko]);
                uint32_t a1 = fbits(aB[ko + 8 * SW1]);
                uint32_t a2 = fbits(aB[ko + 4]);
                uint32_t a3 = fbits(aB[ko + 8 * SW1 + 4]);
#pragma unroll
                for (int s = 0; s < 4; s++) {
                    const float* bp = bB + s * 8 * SW1 + ko;
                    uint32_t b0 = fbits(bp[0]);
                    uint32_t b1 = fbits(bp[4]);
                    MMA_TF32(acc[s], a0, a1, a2, a3, b0, b1);
                }
            }
        }
        // epilogue1: relu, tf32-round, store H (aligned float2)
        {
            int r0 = mi * 16 + gq, r1 = r0 + 8;
#pragma unroll
            for (int s = 0; s < 4; s++) {
                int col0 = ni * 32 + s * 8 + tig * 2;
                float2 u, v;
                u.x = tf32r(fmaxf(acc[s][0], 0.0f));
                u.y = tf32r(fmaxf(acc[s][1], 0.0f));
                v.x = tf32r(fmaxf(acc[s][2], 0.0f));
                v.y = tf32r(fmaxf(acc[s][3], 0.0f));
                *reinterpret_cast<float2*>(sH + r0 * SW2 + col0) = u;
                *reinterpret_cast<float2*>(sH + r1 * SW2 + col0) = v;
            }
        }
        __syncthreads();

        // ================= GEMM2: [64 x 128] @ [128 x 128] =================
        float acc2[4][4];
#pragma unroll
        for (int s = 0; s < 4; s++) {
            int col0 = ni * 32 + s * 8 + tig * 2;
            acc2[s][0] = sb2[col0];
            acc2[s][1] = sb2[col0 + 1];
            acc2[s][2] = acc2[s][0];
            acc2[s][3] = acc2[s][1];
        }
        {
            const float* aB = sH + (mi * 16 + gq) * SW2 + tig;
            const float* bB = sW2 + (ni * 32 + gq) * SW2 + tig;
#pragma unroll 4
            for (int kc = 0; kc < NF / 8; kc++) {
                int ko = kc * 8;
                uint32_t a0 = fbits(aB[ko]);
                uint32_t a1 = fbits(aB[ko + 8 * SW2]);
                uint32_t a2 = fbits(aB[ko + 4]);
                uint32_t a3 = fbits(aB[ko + 8 * SW2 + 4]);
#pragma unroll
                for (int s = 0; s < 4; s++) {
                    const float* bp = bB + s * 8 * SW2 + ko;
                    uint32_t b0 = fbits(bp[0]);
                    uint32_t b1 = fbits(bp[4]);
                    MMA_TF32(acc2[s], a0, a1, a2, a3, b0, b1);
                }
            }
        }
        // epilogue2: relu -> out
        {
            int n0 = base + mi * 16 + gq;
            int n1 = n0 + 8;
#pragma unroll
            for (int s = 0; s < 4; s++) {
                int col0 = ni * 32 + s * 8 + tig * 2;
                if (n0 < N_NODES) {
                    float2 o;
                    o.x = fmaxf(acc2[s][0], 0.0f);
                    o.y = fmaxf(acc2[s][1], 0.0f);
                    *reinterpret_cast<float2*>(out + (size_t)n0 * NF + col0) = o;
                }
                if (n1 < N_NODES) {
                    float2 o;
                    o.x = fmaxf(acc2[s][2], 0.0f);
                    o.y = fmaxf(acc2[s][3], 0.0f);
                    *reinterpret_cast<float2*>(out + (size_t)n1 * NF + col0) = o;
                }
            }
        }

        if (tid == 0) s_tile = atomicAdd(&g_ctr, 1u);
        __syncthreads();
        tile = s_tile;
    }
}

// ---------------------------------------------------------------------------
extern "C" void kernel_launch(void* const* d_in, const int* in_sizes, int n_in,
                              void* d_out, int out_size)
{
    const float* edge_logits = (const float*)d_in[0];
    const float* edge_feats  = (const float*)d_in[1];
    const float* node_feats  = (const float*)d_in[2];
    const int*   dst         = (const int*)d_in[3];
    const float* W_et        = (const float*)d_in[4];
    const float* b_et        = (const float*)d_in[5];
    const float* W1          = (const float*)d_in[6];
    const float* b1          = (const float*)d_in[7];
    const float* W2          = (const float*)d_in[8];
    const float* b2          = (const float*)d_in[9];
    float* out = (float*)d_out;

    static int configured = 0;
    if (!configured) {
        cudaFuncSetAttribute(node_kernel,
                             cudaFuncAttributeMaxDynamicSharedMemorySize, SMEM_BYTES);
        configured = 1;
    }

    init_kernel<<<(NINIT + 255) / 256, 256>>>();
    edge_kernel<<<N_EDGES / 256, 256>>>(edge_logits, edge_feats, dst);
    node_kernel<<<152, 512, SMEM_BYTES>>>(node_feats, W_et, b_et,
                                          W1, b1, W2, b2, out);
}